// round 1
// baseline (speedup 1.0000x reference)
#include <cuda_runtime.h>
#include <cuda_bf16.h>

// Problem constants
#define B_    32
#define CIN_  64
#define COUT_ 64
#define KK_   3
#define ADIM_ 64
#define H_    128
#define W_    128
#define KVOL_ (COUT_*CIN_*KK_*KK_)   // 36864 per sample

// -------- device scratch (no allocation allowed) --------
__device__ float g_pooled[B_ * CIN_];              // [b][cin]
__device__ float g_hid[B_ * ADIM_];                // [b][adim]
// adapted weights in conv-friendly layout: [b][cin][p(=ky*3+kx)][cout]
__device__ float g_wadapt[B_ * CIN_ * 9 * COUT_];  // 4.72 MB

// ============================================================
// Kernel 1: global average pool  x[b][c][H][W] -> pooled[b*64+c]
// ============================================================
__global__ void pool_kernel(const float* __restrict__ x) {
    int plane = blockIdx.x;                  // b*64 + c, 2048 planes
    const float4* p = (const float4*)(x + ((size_t)plane << 14));
    float s = 0.f;
    for (int i = threadIdx.x; i < (H_ * W_ / 4); i += 256) {
        float4 v = p[i];
        s += (v.x + v.y) + (v.z + v.w);
    }
#pragma unroll
    for (int o = 16; o; o >>= 1) s += __shfl_xor_sync(0xffffffffu, s, o);
    __shared__ float red[8];
    if ((threadIdx.x & 31) == 0) red[threadIdx.x >> 5] = s;
    __syncthreads();
    if (threadIdx.x == 0) {
        float t = 0.f;
#pragma unroll
        for (int i = 0; i < 8; i++) t += red[i];
        g_pooled[plane] = t * (1.f / (H_ * W_));
    }
}

// ============================================================
// Kernel 2: h = relu(pooled @ w1 + b1)   [32,64]x[64,64]
// ============================================================
__global__ void mlp1_kernel(const float* __restrict__ w1, const float* __restrict__ b1) {
    __shared__ float sp[B_ * CIN_];      // 2048
    __shared__ float sw[CIN_ * ADIM_];   // 4096
    __shared__ float sb[ADIM_];
    for (int i = threadIdx.x; i < B_ * CIN_; i += 256) sp[i] = g_pooled[i];
    for (int i = threadIdx.x; i < CIN_ * ADIM_; i += 256) sw[i] = w1[i];
    if (threadIdx.x < ADIM_) sb[threadIdx.x] = b1[threadIdx.x];
    __syncthreads();
    for (int idx = threadIdx.x; idx < B_ * ADIM_; idx += 256) {
        int b = idx >> 6, a = idx & 63;
        float acc = sb[a];
#pragma unroll 8
        for (int k = 0; k < CIN_; k++) acc += sp[(b << 6) + k] * sw[(k << 6) + a];
        g_hid[idx] = fmaxf(acc, 0.f);
    }
}

// ============================================================
// Kernel 3: adapted weights
//   a = tanh(h @ w2 + b2);  w_adapt = base_w + scale * a
//   stored transposed as [b][cin][p][cout] for coalesced conv loads
// ============================================================
__global__ void adapt_kernel(const float* __restrict__ base_w,
                             const float* __restrict__ w2,
                             const float* __restrict__ b2,
                             const float* __restrict__ scale_p) {
    int b = blockIdx.y;
    int t = blockIdx.x * 256 + threadIdx.x;   // 0..36863 over (cin,p,cout)
    __shared__ float sh[ADIM_];
    if (threadIdx.x < ADIM_) sh[threadIdx.x] = g_hid[(b << 6) + threadIdx.x];
    __syncthreads();
    int co  = t & 63;
    int cip = t >> 6;                 // cin*9 + p, 0..575
    int col = co * 576 + cip;         // column index in w2 / base_w linear order
    float acc = b2[col];
#pragma unroll 8
    for (int k = 0; k < ADIM_; k++) acc += sh[k] * w2[k * KVOL_ + col];
    g_wadapt[b * KVOL_ + t] = base_w[col] + scale_p[0] * tanhf(acc);
}

// ============================================================
// Kernel 4: per-sample 3x3 conv, pad=1
//   block: b, 4 output rows x 32 output cols, all 64 couts
//   thread: 8 consecutive cols x 4 couts = 32 accumulators
// ============================================================
__global__ void __launch_bounds__(256, 2)
conv_kernel(const float* __restrict__ x,
            const float* __restrict__ base_b,
            float* __restrict__ y) {
    __shared__ float xs[8][6][36];      // 8 cin, 6 halo rows, 34(+2 pad) cols
    __shared__ float ws[8][9][64];      // 8 cin, 9 taps, 64 cout

    const int b  = blockIdx.z;
    const int h0 = blockIdx.y * 4;
    const int w0 = blockIdx.x * 32;
    const int tid = threadIdx.x;
    const int cog = tid >> 4;           // 0..15 : cout group (4 couts)
    const int pg  = tid & 15;           // pixel group
    const int r   = pg >> 2;            // output row within tile 0..3
    const int c0  = (pg & 3) * 8;       // output col start within tile

    float acc[8][4];
#pragma unroll
    for (int m = 0; m < 8; m++)
#pragma unroll
        for (int j = 0; j < 4; j++) acc[m][j] = 0.f;

    const float*  wsrc  = g_wadapt + (size_t)b * KVOL_;
    const float*  xbase = x + ((size_t)(b * CIN_) << 14);

    for (int ci0 = 0; ci0 < CIN_; ci0 += 8) {
        __syncthreads();
        // ---- load x halo tile: 8 cin x 6 rows x 34 cols
        for (int idx = tid; idx < 8 * 6 * 34; idx += 256) {
            int ci  = idx / 204;
            int rem = idx - ci * 204;
            int rr  = rem / 34;
            int cc  = rem - rr * 34;
            int gh = h0 - 1 + rr;
            int gw = w0 - 1 + cc;
            float v = 0.f;
            if ((unsigned)gh < (unsigned)H_ && (unsigned)gw < (unsigned)W_)
                v = xbase[(((ci0 + ci) << 7) + gh << 7) + gw];
            xs[ci][rr][cc] = v;
        }
        // ---- load weight tile: contiguous 8*9*64 floats
        {
            const float4* s4 = (const float4*)(wsrc + ci0 * 576);
            float4* d4 = (float4*)&ws[0][0][0];
            for (int idx = tid; idx < (8 * 9 * 64) / 4; idx += 256) d4[idx] = s4[idx];
        }
        __syncthreads();

#pragma unroll
        for (int ci = 0; ci < 8; ci++) {
            float xv[3][12];
#pragma unroll
            for (int kr = 0; kr < 3; kr++) {
                float4 a0 = *(const float4*)&xs[ci][r + kr][c0];
                float4 a1 = *(const float4*)&xs[ci][r + kr][c0 + 4];
                float4 a2 = *(const float4*)&xs[ci][r + kr][c0 + 8];
                xv[kr][0] = a0.x;  xv[kr][1] = a0.y;  xv[kr][2]  = a0.z;  xv[kr][3]  = a0.w;
                xv[kr][4] = a1.x;  xv[kr][5] = a1.y;  xv[kr][6]  = a1.z;  xv[kr][7]  = a1.w;
                xv[kr][8] = a2.x;  xv[kr][9] = a2.y;  xv[kr][10] = a2.z;  xv[kr][11] = a2.w;
            }
#pragma unroll
            for (int p = 0; p < 9; p++) {
                const int ky = p / 3, kx = p % 3;
                float4 w4 = *(const float4*)&ws[ci][p][cog * 4];
#pragma unroll
                for (int m = 0; m < 8; m++) {
                    float v = xv[ky][kx + m];
                    acc[m][0] += v * w4.x;
                    acc[m][1] += v * w4.y;
                    acc[m][2] += v * w4.z;
                    acc[m][3] += v * w4.w;
                }
            }
        }
    }

    // ---- epilogue: + base_b, vectorized stores
#pragma unroll
    for (int j = 0; j < 4; j++) {
        int co = cog * 4 + j;
        float bb = __ldg(&base_b[co]);
        float* dst = y + (((size_t)(b * COUT_ + co) * H_ + (h0 + r)) * W_ + (w0 + c0));
        float4 o0 = make_float4(acc[0][j] + bb, acc[1][j] + bb, acc[2][j] + bb, acc[3][j] + bb);
        float4 o1 = make_float4(acc[4][j] + bb, acc[5][j] + bb, acc[6][j] + bb, acc[7][j] + bb);
        ((float4*)dst)[0] = o0;
        ((float4*)dst)[1] = o1;
    }
}

// ============================================================
extern "C" void kernel_launch(void* const* d_in, const int* in_sizes, int n_in,
                              void* d_out, int out_size) {
    const float* x      = (const float*)d_in[0];
    const float* base_w = (const float*)d_in[1];
    const float* base_b = (const float*)d_in[2];
    const float* w1     = (const float*)d_in[3];
    const float* b1     = (const float*)d_in[4];
    const float* w2     = (const float*)d_in[5];
    const float* b2     = (const float*)d_in[6];
    const float* scale  = (const float*)d_in[7];
    float* y = (float*)d_out;

    pool_kernel<<<B_ * CIN_, 256>>>(x);
    mlp1_kernel<<<1, 256>>>(w1, b1);
    adapt_kernel<<<dim3(KVOL_ / 256, B_), 256>>>(base_w, w2, b2, scale);
    conv_kernel<<<dim3(W_ / 32, H_ / 4, B_), 256>>>(x, base_b, y);
}

// round 2
// speedup vs baseline: 1.0011x; 1.0011x over previous
#include <cuda_runtime.h>
#include <cuda_bf16.h>

// Problem constants
#define B_    32
#define CIN_  64
#define COUT_ 64
#define KK_   3
#define ADIM_ 64
#define H_    128
#define W_    128
#define KVOL_ (COUT_*CIN_*KK_*KK_)   // 36864 per sample

// -------- device scratch (no allocation allowed) --------
__device__ float g_pooled[B_ * CIN_];              // [b][cin]
__device__ float g_hid[B_ * ADIM_];                // [b][adim]
// adapted weights in conv-friendly layout: [b][cin][p(=ky*3+kx)][cout]
__device__ float g_wadapt[B_ * CIN_ * 9 * COUT_];  // 4.72 MB

// ============================================================
// Kernel 1: global average pool  x[b][c][H][W] -> pooled[b*64+c]
// ============================================================
__global__ void pool_kernel(const float* __restrict__ x) {
    int plane = blockIdx.x;                  // b*64 + c, 2048 planes
    const float4* p = (const float4*)(x + ((size_t)plane << 14));
    float s = 0.f;
    for (int i = threadIdx.x; i < (H_ * W_ / 4); i += 256) {
        float4 v = p[i];
        s += (v.x + v.y) + (v.z + v.w);
    }
#pragma unroll
    for (int o = 16; o; o >>= 1) s += __shfl_xor_sync(0xffffffffu, s, o);
    __shared__ float red[8];
    if ((threadIdx.x & 31) == 0) red[threadIdx.x >> 5] = s;
    __syncthreads();
    if (threadIdx.x == 0) {
        float t = 0.f;
#pragma unroll
        for (int i = 0; i < 8; i++) t += red[i];
        g_pooled[plane] = t * (1.f / (H_ * W_));
    }
}

// ============================================================
// Kernel 2: h = relu(pooled @ w1 + b1)   [32,64]x[64,64]
// ============================================================
__global__ void mlp1_kernel(const float* __restrict__ w1, const float* __restrict__ b1) {
    __shared__ float sp[B_ * CIN_];      // 2048
    __shared__ float sw[CIN_ * ADIM_];   // 4096
    __shared__ float sb[ADIM_];
    for (int i = threadIdx.x; i < B_ * CIN_; i += 256) sp[i] = g_pooled[i];
    for (int i = threadIdx.x; i < CIN_ * ADIM_; i += 256) sw[i] = w1[i];
    if (threadIdx.x < ADIM_) sb[threadIdx.x] = b1[threadIdx.x];
    __syncthreads();
    for (int idx = threadIdx.x; idx < B_ * ADIM_; idx += 256) {
        int b = idx >> 6, a = idx & 63;
        float acc = sb[a];
#pragma unroll 8
        for (int k = 0; k < CIN_; k++) acc += sp[(b << 6) + k] * sw[(k << 6) + a];
        g_hid[idx] = fmaxf(acc, 0.f);
    }
}

// ============================================================
// Kernel 3: adapted weights
//   a = tanh(h @ w2 + b2);  w_adapt = base_w + scale * a
//   stored transposed as [b][cin][p][cout] for coalesced conv loads
// ============================================================
__global__ void adapt_kernel(const float* __restrict__ base_w,
                             const float* __restrict__ w2,
                             const float* __restrict__ b2,
                             const float* __restrict__ scale_p) {
    int b = blockIdx.y;
    int t = blockIdx.x * 256 + threadIdx.x;   // 0..36863 over (cin,p,cout)
    __shared__ float sh[ADIM_];
    if (threadIdx.x < ADIM_) sh[threadIdx.x] = g_hid[(b << 6) + threadIdx.x];
    __syncthreads();
    int co  = t & 63;
    int cip = t >> 6;                 // cin*9 + p, 0..575
    int col = co * 576 + cip;         // column index in w2 / base_w linear order
    float acc = b2[col];
#pragma unroll 8
    for (int k = 0; k < ADIM_; k++) acc += sh[k] * w2[k * KVOL_ + col];
    g_wadapt[b * KVOL_ + t] = base_w[col] + scale_p[0] * tanhf(acc);
}

// ============================================================
// Kernel 4: per-sample 3x3 conv, pad=1
//   block: b, 4 output rows x 32 output cols, all 64 couts
//   thread: 8 consecutive cols x 4 couts = 32 accumulators
// ============================================================
__global__ void __launch_bounds__(256, 2)
conv_kernel(const float* __restrict__ x,
            const float* __restrict__ base_b,
            float* __restrict__ y) {
    __shared__ float xs[8][6][36];      // 8 cin, 6 halo rows, 34(+2 pad) cols
    __shared__ float ws[8][9][64];      // 8 cin, 9 taps, 64 cout

    const int b  = blockIdx.z;
    const int h0 = blockIdx.y * 4;
    const int w0 = blockIdx.x * 32;
    const int tid = threadIdx.x;
    const int cog = tid >> 4;           // 0..15 : cout group (4 couts)
    const int pg  = tid & 15;           // pixel group
    const int r   = pg >> 2;            // output row within tile 0..3
    const int c0  = (pg & 3) * 8;       // output col start within tile

    float acc[8][4];
#pragma unroll
    for (int m = 0; m < 8; m++)
#pragma unroll
        for (int j = 0; j < 4; j++) acc[m][j] = 0.f;

    const float*  wsrc  = g_wadapt + (size_t)b * KVOL_;
    const float*  xbase = x + ((size_t)(b * CIN_) << 14);

    for (int ci0 = 0; ci0 < CIN_; ci0 += 8) {
        __syncthreads();
        // ---- load x halo tile: 8 cin x 6 rows x 34 cols
        for (int idx = tid; idx < 8 * 6 * 34; idx += 256) {
            int ci  = idx / 204;
            int rem = idx - ci * 204;
            int rr  = rem / 34;
            int cc  = rem - rr * 34;
            int gh = h0 - 1 + rr;
            int gw = w0 - 1 + cc;
            float v = 0.f;
            if ((unsigned)gh < (unsigned)H_ && (unsigned)gw < (unsigned)W_)
                v = xbase[(((ci0 + ci) << 7) + gh << 7) + gw];
            xs[ci][rr][cc] = v;
        }
        // ---- load weight tile: contiguous 8*9*64 floats
        {
            const float4* s4 = (const float4*)(wsrc + ci0 * 576);
            float4* d4 = (float4*)&ws[0][0][0];
            for (int idx = tid; idx < (8 * 9 * 64) / 4; idx += 256) d4[idx] = s4[idx];
        }
        __syncthreads();

#pragma unroll
        for (int ci = 0; ci < 8; ci++) {
            float xv[3][12];
#pragma unroll
            for (int kr = 0; kr < 3; kr++) {
                float4 a0 = *(const float4*)&xs[ci][r + kr][c0];
                float4 a1 = *(const float4*)&xs[ci][r + kr][c0 + 4];
                float4 a2 = *(const float4*)&xs[ci][r + kr][c0 + 8];
                xv[kr][0] = a0.x;  xv[kr][1] = a0.y;  xv[kr][2]  = a0.z;  xv[kr][3]  = a0.w;
                xv[kr][4] = a1.x;  xv[kr][5] = a1.y;  xv[kr][6]  = a1.z;  xv[kr][7]  = a1.w;
                xv[kr][8] = a2.x;  xv[kr][9] = a2.y;  xv[kr][10] = a2.z;  xv[kr][11] = a2.w;
            }
#pragma unroll
            for (int p = 0; p < 9; p++) {
                const int ky = p / 3, kx = p % 3;
                float4 w4 = *(const float4*)&ws[ci][p][cog * 4];
#pragma unroll
                for (int m = 0; m < 8; m++) {
                    float v = xv[ky][kx + m];
                    acc[m][0] += v * w4.x;
                    acc[m][1] += v * w4.y;
                    acc[m][2] += v * w4.z;
                    acc[m][3] += v * w4.w;
                }
            }
        }
    }

    // ---- epilogue: + base_b, vectorized stores
#pragma unroll
    for (int j = 0; j < 4; j++) {
        int co = cog * 4 + j;
        float bb = __ldg(&base_b[co]);
        float* dst = y + (((size_t)(b * COUT_ + co) * H_ + (h0 + r)) * W_ + (w0 + c0));
        float4 o0 = make_float4(acc[0][j] + bb, acc[1][j] + bb, acc[2][j] + bb, acc[3][j] + bb);
        float4 o1 = make_float4(acc[4][j] + bb, acc[5][j] + bb, acc[6][j] + bb, acc[7][j] + bb);
        ((float4*)dst)[0] = o0;
        ((float4*)dst)[1] = o1;
    }
}

// ============================================================
extern "C" void kernel_launch(void* const* d_in, const int* in_sizes, int n_in,
                              void* d_out, int out_size) {
    const float* x      = (const float*)d_in[0];
    const float* base_w = (const float*)d_in[1];
    const float* base_b = (const float*)d_in[2];
    const float* w1     = (const float*)d_in[3];
    const float* b1     = (const float*)d_in[4];
    const float* w2     = (const float*)d_in[5];
    const float* b2     = (const float*)d_in[6];
    const float* scale  = (const float*)d_in[7];
    float* y = (float*)d_out;

    pool_kernel<<<B_ * CIN_, 256>>>(x);
    mlp1_kernel<<<1, 256>>>(w1, b1);
    adapt_kernel<<<dim3(KVOL_ / 256, B_), 256>>>(base_w, w2, b2, scale);
    conv_kernel<<<dim3(W_ / 32, H_ / 4, B_), 256>>>(x, base_b, y);
}

// round 5
// speedup vs baseline: 2.6555x; 2.6526x over previous
#include <cuda_runtime.h>
#include <cuda_bf16.h>
#include <cstdint>

#define B_    32
#define CIN_  64
#define COUT_ 64
#define ADIM_ 64
#define H_    128
#define W_    128
#define KVOL_ (COUT_*CIN_*9)

// tcgen05 only exists under arch-specific (sm_103a/sm_100a) compilation.
// The generic compute_103 PTX pass must compile the fallback instead.
#if defined(__CUDA_ARCH_FEAT_SM103_ALL) || defined(__CUDA_ARCH_FEAT_SM100_ALL) || \
    (defined(__CUDA_ARCH_SPECIFIC__))
#define HAS_TCGEN05 1
#else
#define HAS_TCGEN05 0
#endif

// ---------------- device scratch ----------------
__device__ float g_pooled[B_ * CIN_];
__device__ float g_hid[B_ * ADIM_];
// fp32 per-sample weights (fallback path): [b][co][ci][ky][kx]
__device__ float g_wadapt[B_ * KVOL_];
// pre-swizzled bf16 weight tiles: [b][dy][hi/lo] x 24576 bytes (64 rows x 192 k, blocked-atom SW128)
__device__ unsigned char g_wB[B_ * 3 * 2 * 24576];

// ---------------- helpers ----------------
__device__ __forceinline__ uint32_t smem_u32(const void* p) {
    uint32_t a;
    asm("{ .reg .u64 t; cvta.to.shared.u64 t, %1; cvt.u32.u64 %0, t; }" : "=r"(a) : "l"(p));
    return a;
}

// blocked-atom SW128 byte offsets (atom = 8 rows x 64 bf16 = 1024B)
__device__ __forceinline__ uint32_t swzA(int m, int k) {   // 128 rows x 192 k
    uint32_t byte = (uint32_t)(k >> 6) * 16384u + ((uint32_t)(m >> 3) << 10) +
                    ((uint32_t)(m & 7) << 7) + ((uint32_t)(k & 63) << 1);
    return byte ^ ((byte >> 3) & 0x70u);
}
__device__ __forceinline__ uint32_t swzB(int n, int k) {   // 64 rows x 192 k
    uint32_t byte = (uint32_t)(k >> 6) * 8192u + ((uint32_t)(n >> 3) << 10) +
                    ((uint32_t)(n & 7) << 7) + ((uint32_t)(k & 63) << 1);
    return byte ^ ((byte >> 3) & 0x70u);
}

#if HAS_TCGEN05
__device__ __forceinline__ uint32_t elect_one() {
    uint32_t pred;
    asm volatile("{\n\t.reg .pred p;\n\telect.sync _|p, 0xFFFFFFFF;\n\t"
                 "selp.b32 %0, 1, 0, p;\n\t}" : "=r"(pred));
    return pred;
}
#define MBAR_INIT(a, c) asm volatile("mbarrier.init.shared.b64 [%0], %1;" :: "r"(a), "r"(c) : "memory")
#define MBAR_WAIT(a, ph) do {                                                                   \
    uint32_t _m = (a), _p = (ph), _d;                                                           \
    asm volatile("{\n\t.reg .pred p;\n\t"                                                       \
        "mbarrier.try_wait.parity.acquire.cta.shared::cta.b64 p, [%1], %2;\n\t"                 \
        "selp.b32 %0, 1, 0, p;\n\t}" : "=r"(_d) : "r"(_m), "r"(_p) : "memory");                 \
    if (!_d) {                                                                                  \
        asm volatile("{\n\t.reg .pred P1;\n\t"                                                  \
            "WL_%=:\n\t"                                                                        \
            "mbarrier.try_wait.parity.acquire.cta.shared::cta.b64 P1, [%0], %1, 0x989680;\n\t"  \
            "@P1 bra.uni WD_%=;\n\t"                                                            \
            "bra.uni WL_%=;\n\t"                                                                \
            "WD_%=:\n\t}" :: "r"(_m), "r"(_p) : "memory");                                      \
    }                                                                                           \
} while (0)
#define TC_ALLOC(sa, n)   asm volatile("tcgen05.alloc.cta_group::1.sync.aligned.shared::cta.b32 [%0], %1;" :: "r"(sa), "r"(n) : "memory")
#define TC_DEALLOC(t, n)  asm volatile("tcgen05.dealloc.cta_group::1.sync.aligned.b32 %0, %1;" :: "r"(t), "r"(n))
#define TC_COMMIT(mb)     asm volatile("tcgen05.commit.cta_group::1.mbarrier::arrive::one.shared::cluster.b64 [%0];" :: "r"(mb) : "memory")
#define TC_FENCE_AFTER()  asm volatile("tcgen05.fence::after_thread_sync;" ::: "memory")
#define TC_FENCE_BEFORE() asm volatile("tcgen05.fence::before_thread_sync;" ::: "memory")
#define TC_WAIT_LD()      asm volatile("tcgen05.wait::ld.sync.aligned;" ::: "memory")
#define FENCE_ASYNC()     asm volatile("fence.proxy.async.shared::cta;" ::: "memory")

#define TC_LD_X32(r, ta) \
    asm volatile("tcgen05.ld.sync.aligned.32x32b.x32.b32 " \
        "{%0, %1, %2, %3, %4, %5, %6, %7, %8, %9, %10, %11, %12, %13, %14, %15, " \
        "%16, %17, %18, %19, %20, %21, %22, %23, %24, %25, %26, %27, %28, %29, %30, %31}, [%32];" \
        : "=r"((r)[0]),  "=r"((r)[1]),  "=r"((r)[2]),  "=r"((r)[3]), \
          "=r"((r)[4]),  "=r"((r)[5]),  "=r"((r)[6]),  "=r"((r)[7]), \
          "=r"((r)[8]),  "=r"((r)[9]),  "=r"((r)[10]), "=r"((r)[11]), \
          "=r"((r)[12]), "=r"((r)[13]), "=r"((r)[14]), "=r"((r)[15]), \
          "=r"((r)[16]), "=r"((r)[17]), "=r"((r)[18]), "=r"((r)[19]), \
          "=r"((r)[20]), "=r"((r)[21]), "=r"((r)[22]), "=r"((r)[23]), \
          "=r"((r)[24]), "=r"((r)[25]), "=r"((r)[26]), "=r"((r)[27]), \
          "=r"((r)[28]), "=r"((r)[29]), "=r"((r)[30]), "=r"((r)[31]) \
        : "r"(ta))

__device__ __forceinline__ void mma_f16_ss(uint32_t d, uint64_t ad, uint64_t bd,
                                           uint32_t idesc, uint32_t en) {
    asm volatile("{\n\t.reg .pred p;\n\tsetp.ne.u32 p, %5, 0;\n\t"
        "tcgen05.mma.cta_group::1.kind::f16 [%0], %1, %2, %3, {%4, %4, %4, %4}, p;\n\t}"
        :: "r"(d), "l"(ad), "l"(bd), "r"(idesc), "r"(0u), "r"(en) : "memory");
}
__device__ __forceinline__ uint64_t make_desc(uint32_t addr) {
    uint64_t d = (uint64_t(2) << 61) | (uint64_t(1) << 46) |
                 (uint64_t(64) << 32) | (uint64_t(1) << 16);
    return d | ((uint64_t)(addr >> 4) & 0x3FFF);
}
// idesc: F32 accum(bit4), BF16 a(bit7), BF16 b(bit10), N=64 (8<<17), M=128 (8<<24)
#define IDESC_ 0x08100490u
#endif  // HAS_TCGEN05

// ============================================================
// Kernel 1: global average pool
// ============================================================
__global__ void pool_kernel(const float* __restrict__ x) {
    int plane = blockIdx.x;
    const float4* p = (const float4*)(x + ((size_t)plane << 14));
    float s = 0.f;
    for (int i = threadIdx.x; i < (H_ * W_ / 4); i += 256) {
        float4 v = p[i];
        s += (v.x + v.y) + (v.z + v.w);
    }
#pragma unroll
    for (int o = 16; o; o >>= 1) s += __shfl_xor_sync(0xffffffffu, s, o);
    __shared__ float red[8];
    if ((threadIdx.x & 31) == 0) red[threadIdx.x >> 5] = s;
    __syncthreads();
    if (threadIdx.x == 0) {
        float t = 0.f;
#pragma unroll
        for (int i = 0; i < 8; i++) t += red[i];
        g_pooled[plane] = t * (1.f / (H_ * W_));
    }
}

// ============================================================
// Kernel 2: h = relu(pooled @ w1 + b1)
// ============================================================
__global__ void mlp1_kernel(const float* __restrict__ w1, const float* __restrict__ b1) {
    __shared__ float sp[B_ * CIN_];
    __shared__ float sw[CIN_ * ADIM_];
    __shared__ float sb[ADIM_];
    for (int i = threadIdx.x; i < B_ * CIN_; i += 256) sp[i] = g_pooled[i];
    for (int i = threadIdx.x; i < CIN_ * ADIM_; i += 256) sw[i] = w1[i];
    if (threadIdx.x < ADIM_) sb[threadIdx.x] = b1[threadIdx.x];
    __syncthreads();
    for (int idx = threadIdx.x; idx < B_ * ADIM_; idx += 256) {
        int b = idx >> 6, a = idx & 63;
        float acc = sb[a];
#pragma unroll 8
        for (int k = 0; k < CIN_; k++) acc += sp[(b << 6) + k] * sw[(k << 6) + a];
        g_hid[idx] = fmaxf(acc, 0.f);
    }
}

// ============================================================
// Kernel 3: adapted weights -> fp32 (fallback) + bf16 hi/lo swizzled tiles
// ============================================================
__global__ void adapt_kernel(const float* __restrict__ base_w,
                             const float* __restrict__ w2,
                             const float* __restrict__ b2,
                             const float* __restrict__ scale_p) {
    __shared__ float sh[B_][ADIM_ + 1];
    __shared__ float sw2[ADIM_][8];
    int col0 = blockIdx.x * 8;
    for (int i = threadIdx.x; i < B_ * ADIM_; i += 256)
        sh[i >> 6][i & 63] = g_hid[i];
    for (int i = threadIdx.x; i < ADIM_ * 8; i += 256)
        sw2[i >> 3][i & 7] = w2[(size_t)(i >> 3) * KVOL_ + col0 + (i & 7)];
    __syncthreads();
    int j = threadIdx.x >> 5;
    int b = threadIdx.x & 31;
    int col = col0 + j;
    float acc = b2[col];
#pragma unroll
    for (int a = 0; a < ADIM_; a++) acc += sh[b][a] * sw2[a][j];
    float w = base_w[col] + scale_p[0] * tanhf(acc);
    g_wadapt[(size_t)b * KVOL_ + col] = w;
    // col = ((n*64+ci)*3+dy)*3+dx
    int t1 = col / 3, dx = col - 3 * t1;
    int t2 = t1 / 3, dy = t1 - 3 * t2;
    int ci = t2 & 63, n = t2 >> 6;
    __nv_bfloat16 hi = __float2bfloat16(w);
    __nv_bfloat16 lo = __float2bfloat16(w - __bfloat162float(hi));
    uint32_t off = swzB(n, dx * 64 + ci);
    size_t base = (size_t)((b * 3 + dy) * 2) * 24576;
    *(__nv_bfloat16*)(g_wB + base + off) = hi;
    *(__nv_bfloat16*)(g_wB + base + 24576 + off) = lo;
}

// ============================================================
// Kernel 4: tensor-core implicit conv (sm_103a pass)
//   CTA = (b, 8 output rows). 8 D tiles [128px][64co] in TMEM.
//   MMA tile region aligned to 1024B at RUNTIME (static smem shifts
//   the dynamic base; SW128 swizzle needs absolute 1024 alignment).
// ============================================================
#define SM_MBAR     8u
#define SM_SCRATCH  1024u                 // uint32 [130][65] = 33800B
#define SCRATCH_END (1024u + 33800u)      // 34824
// tile region offsets (relative to runtime-aligned tbase)
#define T_AH  0u
#define T_AL  49152u
#define T_BH  98304u
#define T_BL  122880u
#define T_SZ  147456u
#define SM_TOTAL (SCRATCH_END + 1024u + T_SZ)   // 183304 + slack

__global__ void __launch_bounds__(256, 1)
conv_tc_kernel(const float* __restrict__ x,
               const float* __restrict__ base_b,
               float* __restrict__ y) {
#if HAS_TCGEN05
    extern __shared__ unsigned char sm[];
    __shared__ float sbb[COUT_];
    const uint32_t sbase = smem_u32(sm);
    uint32_t* scratch = (uint32_t*)(sm + SM_SCRATCH);

    // runtime 1024B-aligned tile base (absolute smem address space)
    const uint32_t tbase = (sbase + SCRATCH_END + 1023u) & ~1023u;
    unsigned char* tptr = sm + (tbase - sbase);

    const int tid = threadIdx.x;
    const int wid = tid >> 5;
    const int lid = tid & 31;
    const int h0 = blockIdx.x * 8;
    const int b  = blockIdx.y;
    const float* xb = x + ((size_t)b << 20);

    if (tid == 0) MBAR_INIT(sbase + SM_MBAR, 1);
    if (wid == 0) TC_ALLOC(sbase, 512);
    if (tid < COUT_) sbb[tid] = base_b[tid];
    if (tid < 64) { scratch[tid] = 0u; scratch[129 * 65 + tid] = 0u; }  // halo cols
    __syncthreads();
    uint32_t tmem;
    asm volatile("ld.shared.b32 %0, [%1];" : "=r"(tmem) : "r"(sbase));

    const uint64_t dAH = make_desc(tbase + T_AH);
    const uint64_t dAL = make_desc(tbase + T_AL);
    const uint64_t dBH = make_desc(tbase + T_BH);
    const uint64_t dBL = make_desc(tbase + T_BL);

    uint32_t parity = 0;
    int pending = 0;

    for (int dy = 0; dy < 3; dy++) {
        // ---- stage B(dy) hi/lo (pre-swizzled in global: straight copy)
        if (pending) { MBAR_WAIT(sbase + SM_MBAR, parity); parity ^= 1; pending = 0; }
        {
            const uint4* sH = (const uint4*)(g_wB + (size_t)((b * 3 + dy) * 2) * 24576);
            const uint4* sL = sH + (24576 / 16);
            uint4* dH = (uint4*)(tptr + T_BH);
            uint4* dL = (uint4*)(tptr + T_BL);
            for (int i = tid; i < 1536; i += 256) { dH[i] = sH[i]; dL[i] = sL[i]; }
        }

        for (int hh = 0; hh < 8; hh++) {
            // ---- stage scratch: x row (h0+hh+dy-1) transposed+split, packed
            {
                int row = h0 + hh + dy - 1;
                bool valid = (unsigned)row < (unsigned)H_;
                const float* xr = xb + ((size_t)row << 7);
#pragma unroll
                for (int it = 0; it < 32; it++) {
                    int idx = it * 256 + tid;
                    int ci = idx >> 7, w = idx & 127;
                    float v = valid ? xr[((size_t)ci << 14) + w] : 0.f;
                    __nv_bfloat16 hi = __float2bfloat16(v);
                    __nv_bfloat16 lo = __float2bfloat16(v - __bfloat162float(hi));
                    scratch[(w + 1) * 65 + ci] =
                        (uint32_t)__bfloat16_as_ushort(hi) |
                        ((uint32_t)__bfloat16_as_ushort(lo) << 16);
                }
            }
            __syncthreads();
            if (pending) { MBAR_WAIT(sbase + SM_MBAR, parity); parity ^= 1; pending = 0; }

            // ---- build A hi/lo tiles (128 x 192): A[m][dx*64+ci] = scratch[m+dx][ci]
#pragma unroll
            for (int it = 0; it < 4; it++) {
                int item = it * 256 + tid;            // (m, ci0-block)
                int m = item >> 3;
                int ci0 = (item & 7) << 3;
#pragma unroll
                for (int j = 0; j < 3; j++) {
                    const uint32_t* srow = &scratch[(m + j) * 65 + ci0];
                    uint32_t s0 = srow[0], s1 = srow[1], s2 = srow[2], s3 = srow[3];
                    uint32_t s4 = srow[4], s5 = srow[5], s6 = srow[6], s7 = srow[7];
                    uint4 hp, lp;
                    hp.x = __byte_perm(s0, s1, 0x5410); lp.x = __byte_perm(s0, s1, 0x7632);
                    hp.y = __byte_perm(s2, s3, 0x5410); lp.y = __byte_perm(s2, s3, 0x7632);
                    hp.z = __byte_perm(s4, s5, 0x5410); lp.z = __byte_perm(s4, s5, 0x7632);
                    hp.w = __byte_perm(s6, s7, 0x5410); lp.w = __byte_perm(s6, s7, 0x7632);
                    uint32_t off = swzA(m, j * 64 + ci0);
                    *(uint4*)(tptr + T_AH + off) = hp;
                    *(uint4*)(tptr + T_AL + off) = lp;
                }
            }
            __syncthreads();

            // ---- issue MMAs: 3 passes x 12 k-steps into D[hh]
            if (wid == 0) {
                FENCE_ASYNC();
                if (elect_one()) {
                    uint32_t d = tmem + hh * 64;
#pragma unroll
                    for (int s = 0; s < 12; s++) {
                        uint64_t ao = (uint64_t)((s >> 2) * 1024 + (s & 3) * 2);
                        uint64_t bo = (uint64_t)((s >> 2) * 512 + (s & 3) * 2);
                        mma_f16_ss(d, dAH + ao, dBH + bo, IDESC_, !(dy == 0 && s == 0));
                    }
#pragma unroll
                    for (int s = 0; s < 12; s++) {
                        uint64_t ao = (uint64_t)((s >> 2) * 1024 + (s & 3) * 2);
                        uint64_t bo = (uint64_t)((s >> 2) * 512 + (s & 3) * 2);
                        mma_f16_ss(d, dAL + ao, dBH + bo, IDESC_, 1u);
                    }
#pragma unroll
                    for (int s = 0; s < 12; s++) {
                        uint64_t ao = (uint64_t)((s >> 2) * 1024 + (s & 3) * 2);
                        uint64_t bo = (uint64_t)((s >> 2) * 512 + (s & 3) * 2);
                        mma_f16_ss(d, dAH + ao, dBL + bo, IDESC_, 1u);
                    }
                    TC_COMMIT(sbase + SM_MBAR);
                }
            }
            pending = 1;
            __syncthreads();   // scratch reuse barrier (next stage overwrites)
        }
    }

    if (pending) { MBAR_WAIT(sbase + SM_MBAR, parity); parity ^= 1; pending = 0; }
    TC_FENCE_AFTER();

    // ---- epilogue: warp w handles subpartition (w&3), rows hh = 2q + (w>>2)
    {
        int sub = wid & 3, g = wid >> 2;
        int m = sub * 32 + lid;
        float* yb = y + ((size_t)b << 20) + m;
#pragma unroll
        for (int q = 0; q < 4; q++) {
            int hh = q * 2 + g;
            uint32_t r0[32], r1[32];
            TC_LD_X32(r0, tmem + hh * 64);
            TC_LD_X32(r1, tmem + hh * 64 + 32);
            TC_WAIT_LD();
            int h = h0 + hh;
            float* yr = yb + ((size_t)h << 7);
#pragma unroll
            for (int c = 0; c < 32; c++)
                yr[(size_t)c << 14] = __uint_as_float(r0[c]) + sbb[c];
#pragma unroll
            for (int c = 0; c < 32; c++)
                yr[(size_t)(c + 32) << 14] = __uint_as_float(r1[c]) + sbb[c + 32];
        }
    }
    TC_FENCE_BEFORE();
    __syncthreads();
    if (wid == 0) TC_DEALLOC(tmem, 512);

#else  // -------- generic-PTX fallback: correct scalar conv --------
    const int tid = threadIdx.x;
    const int h0 = blockIdx.x * 8;
    const int b  = blockIdx.y;
    const float* xb = x + ((size_t)b << 20);
    const float* wgt_b = g_wadapt + (size_t)b * KVOL_;
    for (int idx = tid; idx < 8 * 128 * 64; idx += 256) {
        int w = idx & 127;
        int rest = idx >> 7;
        int co = rest & 63;
        int hh = rest >> 6;
        int h = h0 + hh;
        float acc = base_b[co];
        const float* wgt = wgt_b + co * 576;
        for (int ci = 0; ci < CIN_; ci++) {
            const float* xp = xb + ((size_t)ci << 14);
            const float* wp = wgt + ci * 9;
            for (int ky = 0; ky < 3; ky++) {
                int ih = h + ky - 1;
                if ((unsigned)ih >= (unsigned)H_) continue;
                for (int kx = 0; kx < 3; kx++) {
                    int iw = w + kx - 1;
                    if ((unsigned)iw >= (unsigned)W_) continue;
                    acc += xp[(ih << 7) + iw] * wp[ky * 3 + kx];
                }
            }
        }
        y[((size_t)b << 20) + ((size_t)co << 14) + ((size_t)h << 7) + w] = acc;
    }
#endif
}

// ============================================================
extern "C" void kernel_launch(void* const* d_in, const int* in_sizes, int n_in,
                              void* d_out, int out_size) {
    const float* x      = (const float*)d_in[0];
    const float* base_w = (const float*)d_in[1];
    const float* base_b = (const float*)d_in[2];
    const float* w1     = (const float*)d_in[3];
    const float* b1     = (const float*)d_in[4];
    const float* w2     = (const float*)d_in[5];
    const float* b2     = (const float*)d_in[6];
    const float* scale  = (const float*)d_in[7];
    float* y = (float*)d_out;

    cudaFuncSetAttribute(conv_tc_kernel,
                         cudaFuncAttributeMaxDynamicSharedMemorySize, SM_TOTAL);

    pool_kernel<<<B_ * CIN_, 256>>>(x);
    mlp1_kernel<<<1, 256>>>(w1, b1);
    adapt_kernel<<<KVOL_ / 8, 256>>>(base_w, w2, b2, scale);
    conv_tc_kernel<<<dim3(H_ / 8, B_), 256, SM_TOTAL>>>(x, base_b, y);
}

// round 6
// speedup vs baseline: 2.7918x; 1.0513x over previous
#include <cuda_runtime.h>
#include <cuda_bf16.h>
#include <cstdint>

#define B_    32
#define CIN_  64
#define COUT_ 64
#define ADIM_ 64
#define H_    128
#define W_    128
#define KVOL_ (COUT_*CIN_*9)

// tcgen05 only exists under arch-specific (sm_103a/sm_100a) compilation.
#if defined(__CUDA_ARCH_FEAT_SM103_ALL) || defined(__CUDA_ARCH_FEAT_SM100_ALL) || \
    (defined(__CUDA_ARCH_SPECIFIC__))
#define HAS_TCGEN05 1
#else
#define HAS_TCGEN05 0
#endif

// ---------------- device scratch ----------------
__device__ float g_pooled[B_ * CIN_];
__device__ float g_hid[B_ * ADIM_];
__device__ float g_wadapt[B_ * KVOL_];   // fp32 weights (fallback path)
// pre-swizzled bf16 weight tiles: [b][dy][hi/lo] x 24576 bytes (64 x 192, blocked-atom SW128)
__device__ unsigned char g_wB[B_ * 3 * 2 * 24576];

// ---------------- helpers ----------------
__device__ __forceinline__ uint32_t smem_u32(const void* p) {
    uint32_t a;
    asm("{ .reg .u64 t; cvta.to.shared.u64 t, %1; cvt.u32.u64 %0, t; }" : "=r"(a) : "l"(p));
    return a;
}
__device__ __forceinline__ uint32_t swzA(int m, int k) {   // 128 rows x 192 k
    uint32_t byte = (uint32_t)(k >> 6) * 16384u + ((uint32_t)(m >> 3) << 10) +
                    ((uint32_t)(m & 7) << 7) + ((uint32_t)(k & 63) << 1);
    return byte ^ ((byte >> 3) & 0x70u);
}
__device__ __forceinline__ uint32_t swzB(int n, int k) {   // 64 rows x 192 k
    uint32_t byte = (uint32_t)(k >> 6) * 8192u + ((uint32_t)(n >> 3) << 10) +
                    ((uint32_t)(n & 7) << 7) + ((uint32_t)(k & 63) << 1);
    return byte ^ ((byte >> 3) & 0x70u);
}

#if HAS_TCGEN05
__device__ __forceinline__ uint32_t elect_one() {
    uint32_t pred;
    asm volatile("{\n\t.reg .pred p;\n\telect.sync _|p, 0xFFFFFFFF;\n\t"
                 "selp.b32 %0, 1, 0, p;\n\t}" : "=r"(pred));
    return pred;
}
#define MBAR_INIT(a, c) asm volatile("mbarrier.init.shared.b64 [%0], %1;" :: "r"(a), "r"(c) : "memory")
#define MBAR_WAIT(a, ph) do {                                                                   \
    uint32_t _m = (a), _p = (ph), _d;                                                           \
    asm volatile("{\n\t.reg .pred p;\n\t"                                                       \
        "mbarrier.try_wait.parity.acquire.cta.shared::cta.b64 p, [%1], %2;\n\t"                 \
        "selp.b32 %0, 1, 0, p;\n\t}" : "=r"(_d) : "r"(_m), "r"(_p) : "memory");                 \
    if (!_d) {                                                                                  \
        asm volatile("{\n\t.reg .pred P1;\n\t"                                                  \
            "WL_%=:\n\t"                                                                        \
            "mbarrier.try_wait.parity.acquire.cta.shared::cta.b64 P1, [%0], %1, 0x989680;\n\t"  \
            "@P1 bra.uni WD_%=;\n\t"                                                            \
            "bra.uni WL_%=;\n\t"                                                                \
            "WD_%=:\n\t}" :: "r"(_m), "r"(_p) : "memory");                                      \
    }                                                                                           \
} while (0)
#define TC_ALLOC(sa, n)   asm volatile("tcgen05.alloc.cta_group::1.sync.aligned.shared::cta.b32 [%0], %1;" :: "r"(sa), "r"(n) : "memory")
#define TC_DEALLOC(t, n)  asm volatile("tcgen05.dealloc.cta_group::1.sync.aligned.b32 %0, %1;" :: "r"(t), "r"(n))
#define TC_COMMIT(mb)     asm volatile("tcgen05.commit.cta_group::1.mbarrier::arrive::one.shared::cluster.b64 [%0];" :: "r"(mb) : "memory")
#define TC_FENCE_AFTER()  asm volatile("tcgen05.fence::after_thread_sync;" ::: "memory")
#define TC_FENCE_BEFORE() asm volatile("tcgen05.fence::before_thread_sync;" ::: "memory")
#define TC_WAIT_LD()      asm volatile("tcgen05.wait::ld.sync.aligned;" ::: "memory")
#define FENCE_ASYNC()     asm volatile("fence.proxy.async.shared::cta;" ::: "memory")

#define TC_LD_X32(r, ta) \
    asm volatile("tcgen05.ld.sync.aligned.32x32b.x32.b32 " \
        "{%0, %1, %2, %3, %4, %5, %6, %7, %8, %9, %10, %11, %12, %13, %14, %15, " \
        "%16, %17, %18, %19, %20, %21, %22, %23, %24, %25, %26, %27, %28, %29, %30, %31}, [%32];" \
        : "=r"((r)[0]),  "=r"((r)[1]),  "=r"((r)[2]),  "=r"((r)[3]), \
          "=r"((r)[4]),  "=r"((r)[5]),  "=r"((r)[6]),  "=r"((r)[7]), \
          "=r"((r)[8]),  "=r"((r)[9]),  "=r"((r)[10]), "=r"((r)[11]), \
          "=r"((r)[12]), "=r"((r)[13]), "=r"((r)[14]), "=r"((r)[15]), \
          "=r"((r)[16]), "=r"((r)[17]), "=r"((r)[18]), "=r"((r)[19]), \
          "=r"((r)[20]), "=r"((r)[21]), "=r"((r)[22]), "=r"((r)[23]), \
          "=r"((r)[24]), "=r"((r)[25]), "=r"((r)[26]), "=r"((r)[27]), \
          "=r"((r)[28]), "=r"((r)[29]), "=r"((r)[30]), "=r"((r)[31]) \
        : "r"(ta))

__device__ __forceinline__ void mma_f16_ss(uint32_t d, uint64_t ad, uint64_t bd,
                                           uint32_t idesc, uint32_t en) {
    asm volatile("{\n\t.reg .pred p;\n\tsetp.ne.u32 p, %5, 0;\n\t"
        "tcgen05.mma.cta_group::1.kind::f16 [%0], %1, %2, %3, {%4, %4, %4, %4}, p;\n\t}"
        :: "r"(d), "l"(ad), "l"(bd), "r"(idesc), "r"(0u), "r"(en) : "memory");
}
__device__ __forceinline__ uint64_t make_desc(uint32_t addr) {
    uint64_t d = (uint64_t(2) << 61) | (uint64_t(1) << 46) |
                 (uint64_t(64) << 32) | (uint64_t(1) << 16);
    return d | ((uint64_t)(addr >> 4) & 0x3FFF);
}
// idesc: F32 accum(bit4), BF16 a(bit7), BF16 b(bit10), N=64 (8<<17), M=128 (8<<24)
#define IDESC_ 0x08100490u
#endif  // HAS_TCGEN05

// ============================================================
// Kernel 1: global average pool
// ============================================================
__global__ void pool_kernel(const float* __restrict__ x) {
    int plane = blockIdx.x;
    const float4* p = (const float4*)(x + ((size_t)plane << 14));
    float s = 0.f;
    for (int i = threadIdx.x; i < (H_ * W_ / 4); i += 256) {
        float4 v = p[i];
        s += (v.x + v.y) + (v.z + v.w);
    }
#pragma unroll
    for (int o = 16; o; o >>= 1) s += __shfl_xor_sync(0xffffffffu, s, o);
    __shared__ float red[8];
    if ((threadIdx.x & 31) == 0) red[threadIdx.x >> 5] = s;
    __syncthreads();
    if (threadIdx.x == 0) {
        float t = 0.f;
#pragma unroll
        for (int i = 0; i < 8; i++) t += red[i];
        g_pooled[plane] = t * (1.f / (H_ * W_));
    }
}

// ============================================================
// Kernel 2: h = relu(pooled @ w1 + b1), one block per sample
// ============================================================
__global__ void mlp1_kernel(const float* __restrict__ w1, const float* __restrict__ b1) {
    int b = blockIdx.x;
    int a = threadIdx.x;     // 64 threads
    __shared__ float sp[CIN_];
    sp[a] = g_pooled[b * CIN_ + a];
    __syncthreads();
    float acc = b1[a];
#pragma unroll 16
    for (int k = 0; k < CIN_; k++) acc += sp[k] * w1[k * ADIM_ + a];
    g_hid[b * ADIM_ + a] = fmaxf(acc, 0.f);
}

// ============================================================
// Kernel 3: adapted weights -> fp32 (fallback) + bf16 hi/lo swizzled tiles
// ============================================================
__global__ void adapt_kernel(const float* __restrict__ base_w,
                             const float* __restrict__ w2,
                             const float* __restrict__ b2,
                             const float* __restrict__ scale_p) {
    __shared__ float sh[B_][ADIM_ + 1];
    __shared__ float sw2[ADIM_][8];
    int col0 = blockIdx.x * 8;
    for (int i = threadIdx.x; i < B_ * ADIM_; i += 256)
        sh[i >> 6][i & 63] = g_hid[i];
    for (int i = threadIdx.x; i < ADIM_ * 8; i += 256)
        sw2[i >> 3][i & 7] = w2[(size_t)(i >> 3) * KVOL_ + col0 + (i & 7)];
    __syncthreads();
    int j = threadIdx.x >> 5;
    int b = threadIdx.x & 31;
    int col = col0 + j;
    float acc = b2[col];
#pragma unroll
    for (int a = 0; a < ADIM_; a++) acc += sh[b][a] * sw2[a][j];
    float w = base_w[col] + scale_p[0] * tanhf(acc);
    g_wadapt[(size_t)b * KVOL_ + col] = w;
    // col = ((n*64+ci)*3+dy)*3+dx
    int t1 = col / 3, dx = col - 3 * t1;
    int t2 = t1 / 3, dy = t1 - 3 * t2;
    int ci = t2 & 63, n = t2 >> 6;
    __nv_bfloat16 hi = __float2bfloat16(w);
    __nv_bfloat16 lo = __float2bfloat16(w - __bfloat162float(hi));
    uint32_t off = swzB(n, dx * 64 + ci);
    size_t base = (size_t)((b * 3 + dy) * 2) * 24576;
    *(__nv_bfloat16*)(g_wB + base + off) = hi;
    *(__nv_bfloat16*)(g_wB + base + 24576 + off) = lo;
}

// ============================================================
// Kernel 4: tensor-core implicit conv (sm_103a), 512 threads
// ============================================================
#define SM_MBAR     8u
#define SM_SCRATCH  1024u                 // uint32 [130][65] = 33800B
#define SCRATCH_END (1024u + 33800u)
#define T_AH  0u
#define T_AL  49152u
#define T_BH  98304u
#define T_BL  122880u
#define T_SZ  147456u
#define SM_TOTAL (SCRATCH_END + 1024u + T_SZ)

#define NTHREADS 512

__global__ void __launch_bounds__(NTHREADS, 1)
conv_tc_kernel(const float* __restrict__ x,
               const float* __restrict__ base_b,
               float* __restrict__ y) {
#if HAS_TCGEN05
    extern __shared__ unsigned char sm[];
    __shared__ float sbb[COUT_];
    const uint32_t sbase = smem_u32(sm);
    uint32_t* scratch = (uint32_t*)(sm + SM_SCRATCH);

    const uint32_t tbase = (sbase + SCRATCH_END + 1023u) & ~1023u;
    unsigned char* tptr = sm + (tbase - sbase);

    const int tid = threadIdx.x;
    const int wid = tid >> 5;
    const int lid = tid & 31;
    const int h0 = blockIdx.x * 8;
    const int b  = blockIdx.y;
    const float* xb = x + ((size_t)b << 20);

    if (tid == 0) MBAR_INIT(sbase + SM_MBAR, 1);
    if (wid == 0) TC_ALLOC(sbase, 512);
    if (tid < COUT_) sbb[tid] = base_b[tid];
    if (tid < 64) { scratch[tid] = 0u; scratch[129 * 65 + tid] = 0u; }  // halo cols
    __syncthreads();
    uint32_t tmem;
    asm volatile("ld.shared.b32 %0, [%1];" : "=r"(tmem) : "r"(sbase));

    const uint64_t dAH = make_desc(tbase + T_AH);
    const uint64_t dAL = make_desc(tbase + T_AL);
    const uint64_t dBH = make_desc(tbase + T_BH);
    const uint64_t dBL = make_desc(tbase + T_BL);

    uint32_t parity = 0;
    int pending = 0;

    for (int dy = 0; dy < 3; dy++) {
        // ---- stage B(dy) hi/lo (pre-swizzled: straight copy)
        if (pending) { MBAR_WAIT(sbase + SM_MBAR, parity); parity ^= 1; pending = 0; }
        {
            const uint4* sH = (const uint4*)(g_wB + (size_t)((b * 3 + dy) * 2) * 24576);
            const uint4* sL = sH + (24576 / 16);
            uint4* dH = (uint4*)(tptr + T_BH);
            uint4* dL = (uint4*)(tptr + T_BL);
            for (int i = tid; i < 1536; i += NTHREADS) { dH[i] = sH[i]; dL[i] = sL[i]; }
        }

        for (int hh = 0; hh < 8; hh++) {
            // ---- stage scratch: x row (h0+hh+dy-1) transposed+split, packed
            {
                int row = h0 + hh + dy - 1;
                bool valid = (unsigned)row < (unsigned)H_;
                const float4* xr4 = (const float4*)(xb + ((size_t)row << 7));
#pragma unroll
                for (int it = 0; it < 4; it++) {
                    int idx = it * NTHREADS + tid;   // 0..2047
                    int ci = idx >> 5;               // 0..63
                    int w4 = idx & 31;               // 0..31
                    float4 v = valid ? xr4[((size_t)ci << 12) + w4]
                                     : make_float4(0.f, 0.f, 0.f, 0.f);
                    float vv[4] = {v.x, v.y, v.z, v.w};
                    int wbase = (w4 << 2) + 1;
#pragma unroll
                    for (int k = 0; k < 4; k++) {
                        __nv_bfloat16 hi = __float2bfloat16(vv[k]);
                        __nv_bfloat16 lo = __float2bfloat16(vv[k] - __bfloat162float(hi));
                        scratch[(wbase + k) * 65 + ci] =
                            (uint32_t)__bfloat16_as_ushort(hi) |
                            ((uint32_t)__bfloat16_as_ushort(lo) << 16);
                    }
                }
            }
            __syncthreads();
            if (pending) { MBAR_WAIT(sbase + SM_MBAR, parity); parity ^= 1; pending = 0; }

            // ---- build A hi/lo tiles (128 x 192): A[m][dx*64+ci] = scratch[m+dx][ci]
#pragma unroll
            for (int it = 0; it < 2; it++) {
                int item = it * NTHREADS + tid;      // 0..1023
                int m = item >> 3;
                int ci0 = (item & 7) << 3;
#pragma unroll
                for (int j = 0; j < 3; j++) {
                    const uint32_t* srow = &scratch[(m + j) * 65 + ci0];
                    uint32_t s0 = srow[0], s1 = srow[1], s2 = srow[2], s3 = srow[3];
                    uint32_t s4 = srow[4], s5 = srow[5], s6 = srow[6], s7 = srow[7];
                    uint4 hp, lp;
                    hp.x = __byte_perm(s0, s1, 0x5410); lp.x = __byte_perm(s0, s1, 0x7632);
                    hp.y = __byte_perm(s2, s3, 0x5410); lp.y = __byte_perm(s2, s3, 0x7632);
                    hp.z = __byte_perm(s4, s5, 0x5410); lp.z = __byte_perm(s4, s5, 0x7632);
                    hp.w = __byte_perm(s6, s7, 0x5410); lp.w = __byte_perm(s6, s7, 0x7632);
                    uint32_t off = swzA(m, j * 64 + ci0);
                    *(uint4*)(tptr + T_AH + off) = hp;
                    *(uint4*)(tptr + T_AL + off) = lp;
                }
            }
            __syncthreads();

            // ---- issue MMAs: 3 passes x 12 k-steps into D[hh]
            if (wid == 0) {
                FENCE_ASYNC();
                if (elect_one()) {
                    uint32_t d = tmem + hh * 64;
#pragma unroll
                    for (int s = 0; s < 12; s++) {
                        uint64_t ao = (uint64_t)((s >> 2) * 1024 + (s & 3) * 2);
                        uint64_t bo = (uint64_t)((s >> 2) * 512 + (s & 3) * 2);
                        mma_f16_ss(d, dAH + ao, dBH + bo, IDESC_, !(dy == 0 && s == 0));
                    }
#pragma unroll
                    for (int s = 0; s < 12; s++) {
                        uint64_t ao = (uint64_t)((s >> 2) * 1024 + (s & 3) * 2);
                        uint64_t bo = (uint64_t)((s >> 2) * 512 + (s & 3) * 2);
                        mma_f16_ss(d, dAL + ao, dBH + bo, IDESC_, 1u);
                    }
#pragma unroll
                    for (int s = 0; s < 12; s++) {
                        uint64_t ao = (uint64_t)((s >> 2) * 1024 + (s & 3) * 2);
                        uint64_t bo = (uint64_t)((s >> 2) * 512 + (s & 3) * 2);
                        mma_f16_ss(d, dAH + ao, dBL + bo, IDESC_, 1u);
                    }
                    TC_COMMIT(sbase + SM_MBAR);
                }
            }
            pending = 1;
            __syncthreads();   // scratch reuse barrier
        }
    }

    if (pending) { MBAR_WAIT(sbase + SM_MBAR, parity); parity ^= 1; pending = 0; }
    TC_FENCE_AFTER();

    // ---- epilogue: 16 warps; warp w: subpartition (w&3), rows hh = (w>>2) + 4q
    {
        int sub = wid & 3, g = wid >> 2;
        int m = sub * 32 + lid;
        float* yb = y + ((size_t)b << 20) + m;
#pragma unroll
        for (int q = 0; q < 2; q++) {
            int hh = g + 4 * q;
            int h = h0 + hh;
            float* yr = yb + ((size_t)h << 7);
            uint32_t r[32];
            TC_LD_X32(r, tmem + hh * 64);
            TC_WAIT_LD();
#pragma unroll
            for (int c = 0; c < 32; c++)
                yr[(size_t)c << 14] = __uint_as_float(r[c]) + sbb[c];
            TC_LD_X32(r, tmem + hh * 64 + 32);
            TC_WAIT_LD();
#pragma unroll
            for (int c = 0; c < 32; c++)
                yr[(size_t)(c + 32) << 14] = __uint_as_float(r[c]) + sbb[c + 32];
        }
    }
    TC_FENCE_BEFORE();
    __syncthreads();
    if (wid == 0) TC_DEALLOC(tmem, 512);

#else  // -------- generic-PTX fallback: correct scalar conv --------
    const int tid = threadIdx.x;
    const int h0 = blockIdx.x * 8;
    const int b  = blockIdx.y;
    const float* xb = x + ((size_t)b << 20);
    const float* wgt_b = g_wadapt + (size_t)b * KVOL_;
    for (int idx = tid; idx < 8 * 128 * 64; idx += NTHREADS) {
        int w = idx & 127;
        int rest = idx >> 7;
        int co = rest & 63;
        int hh = rest >> 6;
        int h = h0 + hh;
        float acc = base_b[co];
        const float* wgt = wgt_b + co * 576;
        for (int ci = 0; ci < CIN_; ci++) {
            const float* xp = xb + ((size_t)ci << 14);
            const float* wp = wgt + ci * 9;
            for (int ky = 0; ky < 3; ky++) {
                int ih = h + ky - 1;
                if ((unsigned)ih >= (unsigned)H_) continue;
                for (int kx = 0; kx < 3; kx++) {
                    int iw = w + kx - 1;
                    if ((unsigned)iw >= (unsigned)W_) continue;
                    acc += xp[(ih << 7) + iw] * wp[ky * 3 + kx];
                }
            }
        }
        y[((size_t)b << 20) + ((size_t)co << 14) + ((size_t)h << 7) + w] = acc;
    }
#endif
}

// ============================================================
extern "C" void kernel_launch(void* const* d_in, const int* in_sizes, int n_in,
                              void* d_out, int out_size) {
    const float* x      = (const float*)d_in[0];
    const float* base_w = (const float*)d_in[1];
    const float* base_b = (const float*)d_in[2];
    const float* w1     = (const float*)d_in[3];
    const float* b1     = (const float*)d_in[4];
    const float* w2     = (const float*)d_in[5];
    const float* b2     = (const float*)d_in[6];
    const float* scale  = (const float*)d_in[7];
    float* y = (float*)d_out;

    cudaFuncSetAttribute(conv_tc_kernel,
                         cudaFuncAttributeMaxDynamicSharedMemorySize, SM_TOTAL);

    pool_kernel<<<B_ * CIN_, 256>>>(x);
    mlp1_kernel<<<B_, 64>>>(w1, b1);
    adapt_kernel<<<KVOL_ / 8, 256>>>(base_w, w2, b2, scale);
    conv_tc_kernel<<<dim3(H_ / 8, B_), NTHREADS, SM_TOTAL>>>(x, base_b, y);
}

// round 8
// speedup vs baseline: 3.4259x; 1.2271x over previous
#include <cuda_runtime.h>
#include <cuda_bf16.h>
#include <cstdint>

#define B_    32
#define CIN_  64
#define COUT_ 64
#define ADIM_ 64
#define H_    128
#define W_    128
#define KVOL_ (COUT_*CIN_*9)

// tcgen05 only exists under arch-specific (sm_103a/sm_100a) compilation.
#if defined(__CUDA_ARCH_FEAT_SM103_ALL) || defined(__CUDA_ARCH_FEAT_SM100_ALL) || \
    (defined(__CUDA_ARCH_SPECIFIC__))
#define HAS_TCGEN05 1
#else
#define HAS_TCGEN05 0
#endif

// ---------------- device scratch ----------------
__device__ float g_pooled[B_ * CIN_];
__device__ float g_hid[B_ * ADIM_];
__device__ float g_wadapt[B_ * KVOL_];   // fp32 weights (fallback path)
// pre-swizzled bf16 weight tiles: [b][dy][hi/lo] x 24576 bytes (64 x 192, blocked-atom SW128)
__device__ unsigned char g_wB[B_ * 3 * 2 * 24576];

// ---------------- helpers ----------------
__device__ __forceinline__ uint32_t smem_u32(const void* p) {
    uint32_t a;
    asm("{ .reg .u64 t; cvta.to.shared.u64 t, %1; cvt.u32.u64 %0, t; }" : "=r"(a) : "l"(p));
    return a;
}
__device__ __forceinline__ uint32_t swzA(int m, int k) {   // 128 rows x 192 k
    uint32_t byte = (uint32_t)(k >> 6) * 16384u + ((uint32_t)(m >> 3) << 10) +
                    ((uint32_t)(m & 7) << 7) + ((uint32_t)(k & 63) << 1);
    return byte ^ ((byte >> 3) & 0x70u);
}
__device__ __forceinline__ uint32_t swzB(int n, int k) {   // 64 rows x 192 k
    uint32_t byte = (uint32_t)(k >> 6) * 8192u + ((uint32_t)(n >> 3) << 10) +
                    ((uint32_t)(n & 7) << 7) + ((uint32_t)(k & 63) << 1);
    return byte ^ ((byte >> 3) & 0x70u);
}

#if HAS_TCGEN05
__device__ __forceinline__ uint32_t elect_one() {
    uint32_t pred;
    asm volatile("{\n\t.reg .pred p;\n\telect.sync _|p, 0xFFFFFFFF;\n\t"
                 "selp.b32 %0, 1, 0, p;\n\t}" : "=r"(pred));
    return pred;
}
#define MBAR_INIT(a, c) asm volatile("mbarrier.init.shared.b64 [%0], %1;" :: "r"(a), "r"(c) : "memory")
#define MBAR_WAIT(a, ph) do {                                                                   \
    uint32_t _m = (a), _p = (ph), _d;                                                           \
    asm volatile("{\n\t.reg .pred p;\n\t"                                                       \
        "mbarrier.try_wait.parity.acquire.cta.shared::cta.b64 p, [%1], %2;\n\t"                 \
        "selp.b32 %0, 1, 0, p;\n\t}" : "=r"(_d) : "r"(_m), "r"(_p) : "memory");                 \
    if (!_d) {                                                                                  \
        asm volatile("{\n\t.reg .pred P1;\n\t"                                                  \
            "WL_%=:\n\t"                                                                        \
            "mbarrier.try_wait.parity.acquire.cta.shared::cta.b64 P1, [%0], %1, 0x989680;\n\t"  \
            "@P1 bra.uni WD_%=;\n\t"                                                            \
            "bra.uni WL_%=;\n\t"                                                                \
            "WD_%=:\n\t}" :: "r"(_m), "r"(_p) : "memory");                                      \
    }                                                                                           \
} while (0)
#define TC_ALLOC(sa, n)   asm volatile("tcgen05.alloc.cta_group::1.sync.aligned.shared::cta.b32 [%0], %1;" :: "r"(sa), "r"(n) : "memory")
#define TC_DEALLOC(t, n)  asm volatile("tcgen05.dealloc.cta_group::1.sync.aligned.b32 %0, %1;" :: "r"(t), "r"(n))
#define TC_COMMIT(mb)     asm volatile("tcgen05.commit.cta_group::1.mbarrier::arrive::one.shared::cluster.b64 [%0];" :: "r"(mb) : "memory")
#define TC_FENCE_AFTER()  asm volatile("tcgen05.fence::after_thread_sync;" ::: "memory")
#define TC_FENCE_BEFORE() asm volatile("tcgen05.fence::before_thread_sync;" ::: "memory")
#define TC_WAIT_LD()      asm volatile("tcgen05.wait::ld.sync.aligned;" ::: "memory")
#define FENCE_ASYNC()     asm volatile("fence.proxy.async.shared::cta;" ::: "memory")

#define TC_LD_X32(r, ta) \
    asm volatile("tcgen05.ld.sync.aligned.32x32b.x32.b32 " \
        "{%0, %1, %2, %3, %4, %5, %6, %7, %8, %9, %10, %11, %12, %13, %14, %15, " \
        "%16, %17, %18, %19, %20, %21, %22, %23, %24, %25, %26, %27, %28, %29, %30, %31}, [%32];" \
        : "=r"((r)[0]),  "=r"((r)[1]),  "=r"((r)[2]),  "=r"((r)[3]), \
          "=r"((r)[4]),  "=r"((r)[5]),  "=r"((r)[6]),  "=r"((r)[7]), \
          "=r"((r)[8]),  "=r"((r)[9]),  "=r"((r)[10]), "=r"((r)[11]), \
          "=r"((r)[12]), "=r"((r)[13]), "=r"((r)[14]), "=r"((r)[15]), \
          "=r"((r)[16]), "=r"((r)[17]), "=r"((r)[18]), "=r"((r)[19]), \
          "=r"((r)[20]), "=r"((r)[21]), "=r"((r)[22]), "=r"((r)[23]), \
          "=r"((r)[24]), "=r"((r)[25]), "=r"((r)[26]), "=r"((r)[27]), \
          "=r"((r)[28]), "=r"((r)[29]), "=r"((r)[30]), "=r"((r)[31]) \
        : "r"(ta))

__device__ __forceinline__ void mma_f16_ss(uint32_t d, uint64_t ad, uint64_t bd,
                                           uint32_t idesc, uint32_t en) {
    asm volatile("{\n\t.reg .pred p;\n\tsetp.ne.u32 p, %5, 0;\n\t"
        "tcgen05.mma.cta_group::1.kind::f16 [%0], %1, %2, %3, {%4, %4, %4, %4}, p;\n\t}"
        :: "r"(d), "l"(ad), "l"(bd), "r"(idesc), "r"(0u), "r"(en) : "memory");
}
__device__ __forceinline__ uint64_t make_desc(uint32_t addr) {
    uint64_t d = (uint64_t(2) << 61) | (uint64_t(1) << 46) |
                 (uint64_t(64) << 32) | (uint64_t(1) << 16);
    return d | ((uint64_t)(addr >> 4) & 0x3FFF);
}
// idesc: F32 accum(bit4), BF16 a(bit7), BF16 b(bit10), N=64 (8<<17), M=128 (8<<24)
#define IDESC_ 0x08100490u
#endif  // HAS_TCGEN05

// ============================================================
// Kernel 1: global average pool
// ============================================================
__global__ void pool_kernel(const float* __restrict__ x) {
    int plane = blockIdx.x;
    const float4* p = (const float4*)(x + ((size_t)plane << 14));
    float s = 0.f;
    for (int i = threadIdx.x; i < (H_ * W_ / 4); i += 256) {
        float4 v = p[i];
        s += (v.x + v.y) + (v.z + v.w);
    }
#pragma unroll
    for (int o = 16; o; o >>= 1) s += __shfl_xor_sync(0xffffffffu, s, o);
    __shared__ float red[8];
    if ((threadIdx.x & 31) == 0) red[threadIdx.x >> 5] = s;
    __syncthreads();
    if (threadIdx.x == 0) {
        float t = 0.f;
#pragma unroll
        for (int i = 0; i < 8; i++) t += red[i];
        g_pooled[plane] = t * (1.f / (H_ * W_));
    }
}

// ============================================================
// Kernel 2: h = relu(pooled @ w1 + b1), one block per sample
// ============================================================
__global__ void mlp1_kernel(const float* __restrict__ w1, const float* __restrict__ b1) {
    int b = blockIdx.x;
    int a = threadIdx.x;     // 64 threads
    __shared__ float sp[CIN_];
    sp[a] = g_pooled[b * CIN_ + a];
    __syncthreads();
    float acc = b1[a];
#pragma unroll 16
    for (int k = 0; k < CIN_; k++) acc += sp[k] * w1[k * ADIM_ + a];
    g_hid[b * ADIM_ + a] = fmaxf(acc, 0.f);
}

// ============================================================
// Kernel 3: adapted weights -> fp32 (fallback) + bf16 hi/lo swizzled tiles
// ============================================================
__global__ void adapt_kernel(const float* __restrict__ base_w,
                             const float* __restrict__ w2,
                             const float* __restrict__ b2,
                             const float* __restrict__ scale_p) {
    __shared__ float sh[B_][ADIM_ + 1];
    __shared__ float sw2[ADIM_][8];
    int col0 = blockIdx.x * 8;
    for (int i = threadIdx.x; i < B_ * ADIM_; i += 256)
        sh[i >> 6][i & 63] = g_hid[i];
    for (int i = threadIdx.x; i < ADIM_ * 8; i += 256)
        sw2[i >> 3][i & 7] = w2[(size_t)(i >> 3) * KVOL_ + col0 + (i & 7)];
    __syncthreads();
    int j = threadIdx.x >> 5;
    int b = threadIdx.x & 31;
    int col = col0 + j;
    float acc = b2[col];
#pragma unroll
    for (int a = 0; a < ADIM_; a++) acc += sh[b][a] * sw2[a][j];
    float w = base_w[col] + scale_p[0] * tanhf(acc);
    g_wadapt[(size_t)b * KVOL_ + col] = w;
    // col = ((n*64+ci)*3+dy)*3+dx
    int t1 = col / 3, dx = col - 3 * t1;
    int t2 = t1 / 3, dy = t1 - 3 * t2;
    int ci = t2 & 63, n = t2 >> 6;
    __nv_bfloat16 hi = __float2bfloat16(w);
    __nv_bfloat16 lo = __float2bfloat16(w - __bfloat162float(hi));
    uint32_t off = swzB(n, dx * 64 + ci);
    size_t base = (size_t)((b * 3 + dy) * 2) * 24576;
    *(__nv_bfloat16*)(g_wB + base + off) = hi;
    *(__nv_bfloat16*)(g_wB + base + 24576 + off) = lo;
}

// ============================================================
// Kernel 4: tensor-core implicit conv (sm_103a), 512 threads
//   R6 skeleton + (a) read-once A-build, (b) LDG hoist of next row,
//   (c) clamped row addresses (no wild pointers, even unFlowed).
// ============================================================
#define SM_MBAR     8u
#define SM_SCRATCH  1024u                 // uint32 [130][65] = 33800B
#define SCRATCH_END (1024u + 33800u)
#define T_AH  0u
#define T_AL  49152u
#define T_BH  98304u
#define T_BL  122880u
#define T_SZ  147456u
#define SM_TOTAL (SCRATCH_END + 1024u + T_SZ)

#define NTHREADS 512
#define NITER    24

__global__ void __launch_bounds__(NTHREADS, 1)
conv_tc_kernel(const float* __restrict__ x,
               const float* __restrict__ base_b,
               float* __restrict__ y) {
#if HAS_TCGEN05
    extern __shared__ unsigned char sm[];
    __shared__ float sbb[COUT_];
    const uint32_t sbase = smem_u32(sm);
    uint32_t* scratch = (uint32_t*)(sm + SM_SCRATCH);

    const uint32_t tbase = (sbase + SCRATCH_END + 1023u) & ~1023u;
    unsigned char* tptr = sm + (tbase - sbase);

    const int tid = threadIdx.x;
    const int wid = tid >> 5;
    const int lid = tid & 31;
    const int h0 = blockIdx.x * 8;
    const int b  = blockIdx.y;
    const float* xb = x + ((size_t)b << 20);

    if (tid == 0) MBAR_INIT(sbase + SM_MBAR, 1);
    if (wid == 0) TC_ALLOC(sbase, 512);
    if (tid < COUT_) sbb[tid] = base_b[tid];
    if (tid < 64) { scratch[tid] = 0u; scratch[129 * 65 + tid] = 0u; }  // halo rows 0,129
    __syncthreads();
    uint32_t tmem;
    asm volatile("ld.shared.b32 %0, [%1];" : "=r"(tmem) : "r"(sbase));

    const uint64_t dAH = make_desc(tbase + T_AH);
    const uint64_t dAL = make_desc(tbase + T_AL);
    const uint64_t dBH = make_desc(tbase + T_BH);
    const uint64_t dBL = make_desc(tbase + T_BL);

    // prefetch mapping: idx = it*512+tid -> ci = idx>>5 (it*16 + tid>>5), w4 = tid&31
    const int pf_w4 = tid & 31;
    const int ci_base = tid >> 5;            // ci = it*16 + ci_base

    float4 v[4];
    // ---- prologue: load row for iter 0 (row = h0-1; clamp, zero-fill)
    {
        int r = h0 - 1;
        bool valid = r >= 0;                  // h0-1 <= 126 < H always
        int rc = valid ? r : 0;
        const float4* xr4 = (const float4*)(xb + ((size_t)rc << 7));
#pragma unroll
        for (int it = 0; it < 4; it++) {
            float4 t = xr4[((size_t)(it * 16 + ci_base) << 12) + pf_w4];
            v[it] = valid ? t : make_float4(0.f, 0.f, 0.f, 0.f);
        }
    }

    uint32_t parity = 0;
    int pending = 0;

    for (int k = 0; k < NITER; k++) {
        const int dy = k >> 3;
        const int hh = k & 7;

        // ---- stage scratch(k) from registers (race-safe: MMA reads A/B only)
#pragma unroll
        for (int it = 0; it < 4; it++) {
            float vv[4] = {v[it].x, v[it].y, v[it].z, v[it].w};
            int ci = it * 16 + ci_base;
            int wbase = (pf_w4 << 2) + 1;
#pragma unroll
            for (int q = 0; q < 4; q++) {
                __nv_bfloat16 hi = __float2bfloat16(vv[q]);
                __nv_bfloat16 lo = __float2bfloat16(vv[q] - __bfloat162float(hi));
                scratch[(wbase + q) * 65 + ci] =
                    (uint32_t)__bfloat16_as_ushort(hi) |
                    ((uint32_t)__bfloat16_as_ushort(lo) << 16);
            }
        }
        __syncthreads();                       // scratch(k) visible

        // ---- hoisted LDG: row for iter k+1 (overlaps wait + build + MMA)
        if (k + 1 < NITER) {
            int kk = k + 1;
            int r = h0 + (kk & 7) + (kk >> 3) - 1;   // >= 0 here (kk>=1)
            bool valid = r < H_;
            int rc = valid ? r : (H_ - 1);
            const float4* xr4 = (const float4*)(xb + ((size_t)rc << 7));
#pragma unroll
            for (int it = 0; it < 4; it++) {
                float4 t = xr4[((size_t)(it * 16 + ci_base) << 12) + pf_w4];
                v[it] = valid ? t : make_float4(0.f, 0.f, 0.f, 0.f);
            }
        }

        if (pending) { MBAR_WAIT(sbase + SM_MBAR, parity); parity ^= 1; pending = 0; }

        // ---- stage B at dy boundary (after wait: prev MMAs done with B)
        if (hh == 0) {
            const uint4* sH = (const uint4*)(g_wB + (size_t)((b * 3 + dy) * 2) * 24576);
            const uint4* sL = sH + (24576 / 16);
            uint4* dH = (uint4*)(tptr + T_BH);
            uint4* dL = (uint4*)(tptr + T_BL);
            for (int i = tid; i < 1536; i += NTHREADS) { dH[i] = sH[i]; dL[i] = sL[i]; }
        }

        // ---- read-once A build: scratch row s -> A[m=s-j][j*64+ci], j=0..2
        for (int item = tid; item < 130 * 8; item += NTHREADS) {
            int s = item >> 3;
            int ci0 = (item & 7) << 3;
            const uint32_t* srow = &scratch[s * 65 + ci0];
            uint32_t s0 = srow[0], s1 = srow[1], s2 = srow[2], s3 = srow[3];
            uint32_t s4 = srow[4], s5 = srow[5], s6 = srow[6], s7 = srow[7];
            uint4 hp, lp;
            hp.x = __byte_perm(s0, s1, 0x5410); lp.x = __byte_perm(s0, s1, 0x7632);
            hp.y = __byte_perm(s2, s3, 0x5410); lp.y = __byte_perm(s2, s3, 0x7632);
            hp.z = __byte_perm(s4, s5, 0x5410); lp.z = __byte_perm(s4, s5, 0x7632);
            hp.w = __byte_perm(s6, s7, 0x5410); lp.w = __byte_perm(s6, s7, 0x7632);
#pragma unroll
            for (int j = 0; j < 3; j++) {
                int m = s - j;
                if ((unsigned)m < 128u) {
                    uint32_t off = swzA(m, j * 64 + ci0);
                    *(uint4*)(tptr + T_AH + off) = hp;
                    *(uint4*)(tptr + T_AL + off) = lp;
                }
            }
        }
        __syncthreads();                       // A (and B) built

        // ---- issue MMAs: 3 passes x 12 k-steps into D[hh]
        if (wid == 0) {
            FENCE_ASYNC();
            if (elect_one()) {
                uint32_t d = tmem + hh * 64;
#pragma unroll
                for (int s = 0; s < 12; s++) {
                    uint64_t ao = (uint64_t)((s >> 2) * 1024 + (s & 3) * 2);
                    uint64_t bo = (uint64_t)((s >> 2) * 512 + (s & 3) * 2);
                    mma_f16_ss(d, dAH + ao, dBH + bo, IDESC_, !(dy == 0 && s == 0));
                }
#pragma unroll
                for (int s = 0; s < 12; s++) {
                    uint64_t ao = (uint64_t)((s >> 2) * 1024 + (s & 3) * 2);
                    uint64_t bo = (uint64_t)((s >> 2) * 512 + (s & 3) * 2);
                    mma_f16_ss(d, dAL + ao, dBH + bo, IDESC_, 1u);
                }
#pragma unroll
                for (int s = 0; s < 12; s++) {
                    uint64_t ao = (uint64_t)((s >> 2) * 1024 + (s & 3) * 2);
                    uint64_t bo = (uint64_t)((s >> 2) * 512 + (s & 3) * 2);
                    mma_f16_ss(d, dAH + ao, dBL + bo, IDESC_, 1u);
                }
                TC_COMMIT(sbase + SM_MBAR);
            }
        }
        pending = 1;
    }

    MBAR_WAIT(sbase + SM_MBAR, parity);
    TC_FENCE_AFTER();

    // ---- epilogue: 16 warps; warp w: subpartition (w&3), rows hh = (w>>2) + 4q
    {
        int sub = wid & 3, g = wid >> 2;
        int m = sub * 32 + lid;
        float* yb = y + ((size_t)b << 20) + m;
#pragma unroll
        for (int q = 0; q < 2; q++) {
            int hh = g + 4 * q;
            int h = h0 + hh;
            float* yr = yb + ((size_t)h << 7);
            uint32_t r[32];
            TC_LD_X32(r, tmem + hh * 64);
            TC_WAIT_LD();
#pragma unroll
            for (int c = 0; c < 32; c++)
                yr[(size_t)c << 14] = __uint_as_float(r[c]) + sbb[c];
            TC_LD_X32(r, tmem + hh * 64 + 32);
            TC_WAIT_LD();
#pragma unroll
            for (int c = 0; c < 32; c++)
                yr[(size_t)(c + 32) << 14] = __uint_as_float(r[c]) + sbb[c + 32];
        }
    }
    TC_FENCE_BEFORE();
    __syncthreads();
    if (wid == 0) TC_DEALLOC(tmem, 512);

#else  // -------- generic-PTX fallback: correct scalar conv --------
    const int tid = threadIdx.x;
    const int h0 = blockIdx.x * 8;
    const int b  = blockIdx.y;
    const float* xb = x + ((size_t)b << 20);
    const float* wgt_b = g_wadapt + (size_t)b * KVOL_;
    for (int idx = tid; idx < 8 * 128 * 64; idx += NTHREADS) {
        int w = idx & 127;
        int rest = idx >> 7;
        int co = rest & 63;
        int hh = rest >> 6;
        int h = h0 + hh;
        float acc = base_b[co];
        const float* wgt = wgt_b + co * 576;
        for (int ci = 0; ci < CIN_; ci++) {
            const float* xp = xb + ((size_t)ci << 14);
            const float* wp = wgt + ci * 9;
            for (int ky = 0; ky < 3; ky++) {
                int ih = h + ky - 1;
                if ((unsigned)ih >= (unsigned)H_) continue;
                for (int kx = 0; kx < 3; kx++) {
                    int iw = w + kx - 1;
                    if ((unsigned)iw >= (unsigned)W_) continue;
                    acc += xp[(ih << 7) + iw] * wp[ky * 3 + kx];
                }
            }
        }
        y[((size_t)b << 20) + ((size_t)co << 14) + ((size_t)h << 7) + w] = acc;
    }
#endif
}

// ============================================================
extern "C" void kernel_launch(void* const* d_in, const int* in_sizes, int n_in,
                              void* d_out, int out_size) {
    const float* x      = (const float*)d_in[0];
    const float* base_w = (const float*)d_in[1];
    const float* base_b = (const float*)d_in[2];
    const float* w1     = (const float*)d_in[3];
    const float* b1     = (const float*)d_in[4];
    const float* w2     = (const float*)d_in[5];
    const float* b2     = (const float*)d_in[6];
    const float* scale  = (const float*)d_in[7];
    float* y = (float*)d_out;

    cudaFuncSetAttribute(conv_tc_kernel,
                         cudaFuncAttributeMaxDynamicSharedMemorySize, SM_TOTAL);

    pool_kernel<<<B_ * CIN_, 256>>>(x);
    mlp1_kernel<<<B_, 64>>>(w1, b1);
    adapt_kernel<<<KVOL_ / 8, 256>>>(base_w, w2, b2, scale);
    conv_tc_kernel<<<dim3(H_ / 8, B_), NTHREADS, SM_TOTAL>>>(x, base_b, y);
}